// round 12
// baseline (speedup 1.0000x reference)
#include <cuda_runtime.h>

// YOLOLoss fused, round 12: R11 structure with supported reduction (SHFL chain;
// redux.sync.add.f32 doesn't exist on sm_103a).
// 352 blocks x 512 threads (2 batches per block -> half the tails),
// plain-store per-warp dense partials, single fence+counter tail.

#define BSZ     32
#define NT      50
#define HH      104
#define WW      104
#define HW      (HH*WW)                 // 10816
#define NCLS    20
#define BLK_POS 512                     // 256 thr-per-batch x 2 positions
#define NBX     ((HW + BLK_POS - 1) / BLK_POS)   // 22
#define NBLK    (NBX * (BSZ/2))         // 352 (two batches per block)
#define NCELL   ((double)(BSZ * 3 * HW))

__device__ double   g_acc[8];           // zero-init; reset by finalizer
__device__ unsigned g_ctr;

// min(softplus(z), 100) == -clip(log(1-sigmoid(z)), -100); spl(-z) == -clip(log(sigmoid(z)), -100)
__device__ __forceinline__ float spl(float z) {
    return fminf(__logf(1.0f + __expf(z)), 100.0f);
}

__global__ __launch_bounds__(512)
void yolo_fused(const float* __restrict__ in, const float* __restrict__ tg,
                float* __restrict__ out)
{
    __shared__ int   s_meta[2][NT];     // per half-block batch
    __shared__ float s_acc[8];          // sparse terms (atomic, few writers)
    __shared__ float s_no[16];          // per-warp dense partials (plain stores)
    __shared__ int   s_last;

    const int tid  = threadIdx.x;
    const int half = tid >> 8;          // 0 or 1 -> which batch
    const int htid = tid & 255;         // thread id within half
    const int b    = blockIdx.y * 2 + half;
    const int P0   = blockIdx.x * BLK_POS;
    const int lane = tid & 31, wrp = tid >> 5;

    // ---- dense conf loads: 2 positions x 3 anchors, issued first ----
    const int  p0   = P0 + htid * 2;
    const bool live = (p0 < HW);        // HW even -> full pairs
    const float* base = in + (size_t)b * 75 * HW;
    float2 c0, c1, c2;
    if (live) {
        c0 = *(const float2*)(base + (size_t)( 4) * HW + p0);
        c1 = *(const float2*)(base + (size_t)(29) * HW + p0);
        c2 = *(const float2*)(base + (size_t)(54) * HW + p0);
    }
    if (tid < 8) s_acc[tid] = 0.0f;

    // ---- per-target prologue (htid 0..49 of each half) ----
    int  mymeta = 0;
    bool inr = false;
    float mytx = 0.f, myty = 0.f, mytw = 0.f, myth = 0.f;
    if (htid < NT) {
        const float* t = tg + ((size_t)b * NT + htid) * 5;
        float t0 = t[0], t1 = t[1], t2 = t[2], t3 = t[3], t4 = t[4];
        int meta = 0x7FFFFFFF;          // invalid: low14 = 16383 > any pos
        if (t0 + t1 + t2 + t3 + t4 > 0.0f) {
            float gx = t0 * (float)WW, gy = t1 * (float)HH;
            float gw = t2 * (float)WW, gh = t3 * (float)HH;
            int gi = (int)gx, gj = (int)gy;
            const float aw[3] = {14.5f, 19.5f, 46.625f};   // ANCHORS / 8
            const float ah[3] = {11.25f, 24.75f, 40.75f};
            float area = (gw + 1.0f) * (gh + 1.0f);
            float best = -1.0f; int bn = 0, nz = 0;
            #pragma unroll
            for (int a = 0; a < 3; a++) {
                float inter = fmaxf(fminf(gw, aw[a]) + 1.0f, 0.0f) *
                              fmaxf(fminf(gh, ah[a]) + 1.0f, 0.0f);
                float iou = inter / (area + (aw[a] + 1.0f) * (ah[a] + 1.0f) - inter + 1e-16f);
                if (iou > best) { best = iou; bn = a; }      // first max wins
                if (iou > 0.5f) nz |= (1 << a);
            }
            mytx = gx - (float)gi;
            myty = gy - (float)gj;
            mytw = __logf(gw / aw[bn] + 1e-16f);
            myth = __logf(gh / ah[bn] + 1e-16f);
            int pos = gj * WW + gi;
            meta = pos | (bn << 14) | (nz << 16) | (((int)t4) << 19);
            inr = (pos >= P0) && (pos < P0 + BLK_POS);
        }
        s_meta[half][htid] = meta;
        mymeta = meta;
    }

    // ---- speculative loads for in-range targets (pre-barrier) ----
    float vx = 0, vy = 0, vw = 0, vh = 0, vc = 0, cfa0 = 0, cfa1 = 0, cfa2 = 0;
    int   mypos = 0, mya = 0;
    if (inr) {
        mypos = mymeta & 0x3FFF;
        mya   = (mymeta >> 14) & 3;
        const float* ch = base + (size_t)(mya * 25) * HW + mypos;
        vx = ch[0]; vy = ch[HW]; vw = ch[2 * HW]; vh = ch[3 * HW]; vc = ch[4 * HW];
        cfa0 = base[(size_t)( 4) * HW + mypos];
        cfa1 = base[(size_t)(29) * HW + mypos];
        cfa2 = base[(size_t)(54) * HW + mypos];
    }

    // ---- dense math: log of products (6 EX2 + 1 LG2), warp SHFL reduce ----
    float a_no = 0.0f;
    if (live) {
        float e0 = __expf(c0.x), e1 = __expf(c0.y);
        float e2 = __expf(c1.x), e3 = __expf(c1.y);
        float e4 = __expf(c2.x), e5 = __expf(c2.y);
        float P = (1.0f + e0);
        P = fmaf(P, e1, P);             // P *= (1+e_k)
        P = fmaf(P, e2, P);
        P = fmaf(P, e3, P);
        P = fmaf(P, e4, P);
        P = fmaf(P, e5, P);
        a_no = __logf(P);               // == sum of 6 softplus values
    }
    #pragma unroll
    for (int off = 16; off > 0; off >>= 1)
        a_no += __shfl_down_sync(0xFFFFFFFFu, a_no, off);
    if (lane == 0) s_no[wrp] = a_no;    // plain store, own slot

    __syncthreads();                    // s_acc zeroed, s_meta published, s_no ready

    // ---- target resolution: dedup survivors, class union, unique ignore bits ----
    if (inr) {
        int      mynz  = (mymeta >> 16) & 7;
        unsigned cm    = 1u << ((mymeta >> 19) & 31);
        bool     alive = true;
        int      subnz = mynz;
        for (int u = 0; u < NT; u++) {
            if (u == htid) continue;
            int mu = s_meta[half][u];
            if ((mu & 0x3FFF) != mypos) continue;
            if (((mu >> 14) & 3) == mya) {
                if (u > htid) alive = false;                 // last duplicate wins
                else          cm |= 1u << ((mu >> 19) & 31); // union earlier classes
            }
            if (u < htid) subnz &= ~((mu >> 16) & 7);        // earlier owner subtracts
        }
        float sub = 0.0f;               // remove ignored cells from dense sum
        if (subnz & 1) sub += spl(cfa0);
        if (subnz & 2) sub += spl(cfa1);
        if (subnz & 4) sub += spl(cfa2);
        if (sub != 0.0f) atomicAdd(&s_acc[5], -sub);

        if (alive) {
            const float* ch = base + (size_t)(mya * 25) * HW + mypos;
            float pc[NCLS];
            #pragma unroll
            for (int c = 0; c < NCLS; c++) pc[c] = ch[(size_t)(5 + c) * HW];
            float scl = 0.0f;
            #pragma unroll
            for (int c = 0; c < NCLS; c++)
                scl += spl(((cm >> c) & 1) ? -pc[c] : pc[c]);
            // BCE(sigm(z), t) = t*spl(-z) + (1-t)*spl(z)
            atomicAdd(&s_acc[0], mytx * spl(-vx) + (1.0f - mytx) * spl(vx));
            atomicAdd(&s_acc[1], myty * spl(-vy) + (1.0f - myty) * spl(vy));
            float dw = vw - mytw, dh = vh - myth;
            atomicAdd(&s_acc[2], dw * dw);
            atomicAdd(&s_acc[3], dh * dh);
            atomicAdd(&s_acc[4], spl(-vc));
            atomicAdd(&s_acc[6], scl);
            atomicAdd(&s_acc[7], 1.0f);
        }
    }
    __syncthreads();

    // ---- global accumulation + counter (one tail per 352 blocks) ----
    if (tid < 8) {
        float v = s_acc[tid];
        if (tid == 5) {
            #pragma unroll
            for (int w16 = 0; w16 < 16; w16++) v += s_no[w16];
        }
        if (v != 0.0f) atomicAdd(&g_acc[tid], (double)v);
        __threadfence();                // order REDG before counter
    }
    __syncthreads();
    if (tid == 0) s_last = (atomicAdd(&g_ctr, 1) == NBLK - 1);
    __syncthreads();

    if (s_last && tid == 0) {
        __threadfence();
        double A[8];
        #pragma unroll
        for (int i = 0; i < 8; i++) A[i] = atomicAdd(&g_acc[i], 0.0);  // coherent read
        out[0] = (float)(2.5 * A[0] / NCELL);
        out[1] = (float)(2.5 * A[1] / NCELL);
        out[2] = (float)(2.5 * A[2] / NCELL);
        out[3] = (float)(2.5 * A[3] / NCELL);
        out[4] = (float)((A[4] + 0.5 * A[5]) / NCELL);
        out[5] = (float)(A[6] / fmax(A[7] * 20.0, 1.0));
        #pragma unroll
        for (int i = 0; i < 8; i++) g_acc[i] = 0.0;    // reset for next replay
        __threadfence();
        g_ctr = 0;
    }
}

extern "C" void kernel_launch(void* const* d_in, const int* in_sizes, int n_in,
                              void* d_out, int out_size) {
    const float* in = (const float*)d_in[0];   // (32,75,104,104)
    const float* tg = (const float*)d_in[1];   // (32,50,5)
    float* out = (float*)d_out;                // 6 floats

    dim3 grid(NBX, BSZ / 2);                   // (22, 16) = 352 blocks x 512 thr
    yolo_fused<<<grid, 512>>>(in, tg, out);
}

// round 13
// speedup vs baseline: 1.0019x; 1.0019x over previous
#include <cuda_runtime.h>

// YOLOLoss fused, round 13: R12 + tail-ectomy.
// 352 blocks x 512 threads (2 batches/block). Tail handled entirely by warp 0:
// no s_last broadcast, no extra block barriers, parallel (MLP=8) finalize reads.

#define BSZ     32
#define NT      50
#define HH      104
#define WW      104
#define HW      (HH*WW)                 // 10816
#define NCLS    20
#define BLK_POS 512                     // 256 thr-per-batch x 2 positions
#define NBX     ((HW + BLK_POS - 1) / BLK_POS)   // 22
#define NBLK    (NBX * (BSZ/2))         // 352
#define NCELL   ((double)(BSZ * 3 * HW))

__device__ double   g_acc[8];           // zero-init; reset by finalizer
__device__ unsigned g_ctr;

// min(softplus(z), 100) == -clip(log(1-sigmoid(z)), -100); spl(-z) == -clip(log(sigmoid(z)), -100)
__device__ __forceinline__ float spl(float z) {
    return fminf(__logf(1.0f + __expf(z)), 100.0f);
}

__global__ __launch_bounds__(512)
void yolo_fused(const float* __restrict__ in, const float* __restrict__ tg,
                float* __restrict__ out)
{
    __shared__ int   s_meta[2][NT];     // per half-block batch
    __shared__ float s_acc[8];          // sparse terms (atomic, few writers)
    __shared__ float s_no[16];          // per-warp dense partials (plain stores)

    const int tid  = threadIdx.x;
    const int half = tid >> 8;          // 0 or 1 -> which batch
    const int htid = tid & 255;         // thread id within half
    const int b    = blockIdx.y * 2 + half;
    const int P0   = blockIdx.x * BLK_POS;
    const int lane = tid & 31, wrp = tid >> 5;

    // ---- dense conf loads: 2 positions x 3 anchors, issued first ----
    const int  p0   = P0 + htid * 2;
    const bool live = (p0 < HW);        // HW even -> full pairs
    const float* base = in + (size_t)b * 75 * HW;
    float2 c0, c1, c2;
    if (live) {
        c0 = *(const float2*)(base + (size_t)( 4) * HW + p0);
        c1 = *(const float2*)(base + (size_t)(29) * HW + p0);
        c2 = *(const float2*)(base + (size_t)(54) * HW + p0);
    }
    if (tid < 8) s_acc[tid] = 0.0f;

    // ---- per-target prologue (htid 0..49 of each half) ----
    int  mymeta = 0;
    bool inr = false;
    float mytx = 0.f, myty = 0.f, mytw = 0.f, myth = 0.f;
    if (htid < NT) {
        const float* t = tg + ((size_t)b * NT + htid) * 5;
        float t0 = t[0], t1 = t[1], t2 = t[2], t3 = t[3], t4 = t[4];
        int meta = 0x7FFFFFFF;          // invalid: low14 = 16383 > any pos
        if (t0 + t1 + t2 + t3 + t4 > 0.0f) {
            float gx = t0 * (float)WW, gy = t1 * (float)HH;
            float gw = t2 * (float)WW, gh = t3 * (float)HH;
            int gi = (int)gx, gj = (int)gy;
            const float aw[3] = {14.5f, 19.5f, 46.625f};   // ANCHORS / 8
            const float ah[3] = {11.25f, 24.75f, 40.75f};
            float area = (gw + 1.0f) * (gh + 1.0f);
            float best = -1.0f; int bn = 0, nz = 0;
            #pragma unroll
            for (int a = 0; a < 3; a++) {
                float inter = fmaxf(fminf(gw, aw[a]) + 1.0f, 0.0f) *
                              fmaxf(fminf(gh, ah[a]) + 1.0f, 0.0f);
                float iou = inter / (area + (aw[a] + 1.0f) * (ah[a] + 1.0f) - inter + 1e-16f);
                if (iou > best) { best = iou; bn = a; }      // first max wins
                if (iou > 0.5f) nz |= (1 << a);
            }
            mytx = gx - (float)gi;
            myty = gy - (float)gj;
            mytw = __logf(gw / aw[bn] + 1e-16f);
            myth = __logf(gh / ah[bn] + 1e-16f);
            int pos = gj * WW + gi;
            meta = pos | (bn << 14) | (nz << 16) | (((int)t4) << 19);
            inr = (pos >= P0) && (pos < P0 + BLK_POS);
        }
        s_meta[half][htid] = meta;
        mymeta = meta;
    }

    // ---- speculative loads for in-range targets (pre-barrier) ----
    float vx = 0, vy = 0, vw = 0, vh = 0, vc = 0, cfa0 = 0, cfa1 = 0, cfa2 = 0;
    int   mypos = 0, mya = 0;
    if (inr) {
        mypos = mymeta & 0x3FFF;
        mya   = (mymeta >> 14) & 3;
        const float* ch = base + (size_t)(mya * 25) * HW + mypos;
        vx = ch[0]; vy = ch[HW]; vw = ch[2 * HW]; vh = ch[3 * HW]; vc = ch[4 * HW];
        cfa0 = base[(size_t)( 4) * HW + mypos];
        cfa1 = base[(size_t)(29) * HW + mypos];
        cfa2 = base[(size_t)(54) * HW + mypos];
    }

    // ---- dense math: log of products (6 EX2 + 1 LG2), warp SHFL reduce ----
    float a_no = 0.0f;
    if (live) {
        float e0 = __expf(c0.x), e1 = __expf(c0.y);
        float e2 = __expf(c1.x), e3 = __expf(c1.y);
        float e4 = __expf(c2.x), e5 = __expf(c2.y);
        float P = (1.0f + e0);
        P = fmaf(P, e1, P);             // P *= (1+e_k)
        P = fmaf(P, e2, P);
        P = fmaf(P, e3, P);
        P = fmaf(P, e4, P);
        P = fmaf(P, e5, P);
        a_no = __logf(P);               // == sum of 6 softplus values
    }
    #pragma unroll
    for (int off = 16; off > 0; off >>= 1)
        a_no += __shfl_down_sync(0xFFFFFFFFu, a_no, off);
    if (lane == 0) s_no[wrp] = a_no;    // plain store, own slot

    __syncthreads();                    // s_acc zeroed, s_meta + s_no published

    // ---- target resolution: dedup survivors, class union, unique ignore bits ----
    if (inr) {
        int      mynz  = (mymeta >> 16) & 7;
        unsigned cm    = 1u << ((mymeta >> 19) & 31);
        bool     alive = true;
        int      subnz = mynz;
        for (int u = 0; u < NT; u++) {
            if (u == htid) continue;
            int mu = s_meta[half][u];
            if ((mu & 0x3FFF) != mypos) continue;
            if (((mu >> 14) & 3) == mya) {
                if (u > htid) alive = false;                 // last duplicate wins
                else          cm |= 1u << ((mu >> 19) & 31); // union earlier classes
            }
            if (u < htid) subnz &= ~((mu >> 16) & 7);        // earlier owner subtracts
        }
        float sub = 0.0f;               // remove ignored cells from dense sum
        if (subnz & 1) sub += spl(cfa0);
        if (subnz & 2) sub += spl(cfa1);
        if (subnz & 4) sub += spl(cfa2);
        if (sub != 0.0f) atomicAdd(&s_acc[5], -sub);

        if (alive) {
            const float* ch = base + (size_t)(mya * 25) * HW + mypos;
            float pc[NCLS];
            #pragma unroll
            for (int c = 0; c < NCLS; c++) pc[c] = ch[(size_t)(5 + c) * HW];
            float scl = 0.0f;
            #pragma unroll
            for (int c = 0; c < NCLS; c++)
                scl += spl(((cm >> c) & 1) ? -pc[c] : pc[c]);
            // BCE(sigm(z), t) = t*spl(-z) + (1-t)*spl(z)
            atomicAdd(&s_acc[0], mytx * spl(-vx) + (1.0f - mytx) * spl(vx));
            atomicAdd(&s_acc[1], myty * spl(-vy) + (1.0f - myty) * spl(vy));
            float dw = vw - mytw, dh = vh - myth;
            atomicAdd(&s_acc[2], dw * dw);
            atomicAdd(&s_acc[3], dh * dh);
            atomicAdd(&s_acc[4], spl(-vc));
            atomicAdd(&s_acc[6], scl);
            atomicAdd(&s_acc[7], 1.0f);
        }
    }
    __syncthreads();                    // s_acc final; LAST block-wide barrier

    // ---- tail: warp 0 only (other warps exit) ----
    if (wrp == 0) {
        // lanes 0..7: accumulate block partial to global
        float v = 0.0f;
        if (lane < 8) {
            v = s_acc[lane];
            if (lane == 5) {
                #pragma unroll
                for (int w16 = 0; w16 < 16; w16++) v += s_no[w16];
            }
            if (v != 0.0f) atomicAdd(&g_acc[lane], (double)v);
        }
        __threadfence();                // each lane orders its own REDG
        __syncwarp();                   // all lanes' fences done before counter

        int last = 0;
        if (lane == 0) last = (atomicAdd(&g_ctr, 1) == NBLK - 1);
        last = __shfl_sync(0xFFFFFFFFu, last, 0);

        if (last) {
            __threadfence();
            double A = 0.0;
            if (lane < 8) {
                A = atomicAdd(&g_acc[lane], 0.0);    // parallel coherent reads (MLP=8)
                g_acc[lane] = 0.0;                   // reset for next replay
            }
            // gather the 8 accumulators to lane 0
            double A0 = __shfl_sync(0xFFFFFFFFu, A, 0);
            double A1 = __shfl_sync(0xFFFFFFFFu, A, 1);
            double A2 = __shfl_sync(0xFFFFFFFFu, A, 2);
            double A3 = __shfl_sync(0xFFFFFFFFu, A, 3);
            double A4 = __shfl_sync(0xFFFFFFFFu, A, 4);
            double A5 = __shfl_sync(0xFFFFFFFFu, A, 5);
            double A6 = __shfl_sync(0xFFFFFFFFu, A, 6);
            double A7 = __shfl_sync(0xFFFFFFFFu, A, 7);
            if (lane == 0) {
                out[0] = (float)(2.5 * A0 / NCELL);
                out[1] = (float)(2.5 * A1 / NCELL);
                out[2] = (float)(2.5 * A2 / NCELL);
                out[3] = (float)(2.5 * A3 / NCELL);
                out[4] = (float)((A4 + 0.5 * A5) / NCELL);
                out[5] = (float)(A6 / fmax(A7 * 20.0, 1.0));
                __threadfence();
                g_ctr = 0;
            }
        }
    }
}

extern "C" void kernel_launch(void* const* d_in, const int* in_sizes, int n_in,
                              void* d_out, int out_size) {
    const float* in = (const float*)d_in[0];   // (32,75,104,104)
    const float* tg = (const float*)d_in[1];   // (32,50,5)
    float* out = (float*)d_out;                // 6 floats

    dim3 grid(NBX, BSZ / 2);                   // (22, 16) = 352 blocks x 512 thr
    yolo_fused<<<grid, 512>>>(in, tg, out);
}